// round 4
// baseline (speedup 1.0000x reference)
#include <cuda_runtime.h>

#define MAXN   10048
#define MAXCB  157
#define MAXP   1000
#define NBUCK  65536

// ---- static device scratch (no allocations allowed) ----
__device__ unsigned long long g_mask[(size_t)MAXN * MAXCB];  // suppression bitmask rows
__device__ unsigned long long g_diag[MAXN];                  // compact diagonal-block masks
__device__ float4             g_sboxes[MAXN];                // boxes in sorted order
__device__ float              g_sscores[MAXN];               // scores in sorted order
__device__ unsigned long long g_keep[MAXCB];                 // keep bits per 64-chunk
__device__ int                g_prefix[MAXCB];               // kept-count prefix per chunk
__device__ int                g_cnt[NBUCK];                  // bucket histogram
__device__ int                g_fill[NBUCK];                 // bucket fill cursors
__device__ int                g_base[NBUCK];                 // bucket base (descending order)
__device__ int                g_members[MAXN];               // indices grouped by bucket

// ---------------------------------------------------------------------------
// S0: clear histogram + fill cursors (graph replays reuse static buffers)
// ---------------------------------------------------------------------------
__global__ void k_clear() {
    int i = blockIdx.x * blockDim.x + threadIdx.x;
    if (i < NBUCK) { g_cnt[i] = 0; g_fill[i] = 0; }
}

// ---------------------------------------------------------------------------
// S1: histogram of score buckets (top 16 bits of float bits; monotonic for
// non-negative floats).
// ---------------------------------------------------------------------------
__global__ void k_hist(const float* __restrict__ scores, int N) {
    int i = blockIdx.x * blockDim.x + threadIdx.x;
    if (i >= N) return;
    unsigned b = __float_as_uint(scores[i]) >> 16;
    atomicAdd(&g_cnt[b], 1);
}

// ---------------------------------------------------------------------------
// S2: single-block exclusive scan over buckets in DESCENDING bucket order:
// g_base[b] = #elements in buckets > b  (= start position of bucket b in the
// descending-score sorted output).
// ---------------------------------------------------------------------------
__global__ void k_scanhist() {
    __shared__ int part[1024];
    int t = threadIdx.x;
    int rb0 = t * 64;  // rb = descending-order index: rb = 65535 - b
    int sum = 0;
    #pragma unroll
    for (int k = 0; k < 64; k++) sum += g_cnt[NBUCK - 1 - (rb0 + k)];
    part[t] = sum;
    __syncthreads();
    // Hillis-Steele inclusive scan over 1024 partials
    for (int off = 1; off < 1024; off <<= 1) {
        int tmp = (t >= off) ? part[t - off] : 0;
        __syncthreads();
        part[t] += tmp;
        __syncthreads();
    }
    int run = part[t] - sum;  // exclusive base for this thread's range
    #pragma unroll
    for (int k = 0; k < 64; k++) {
        int b = NBUCK - 1 - (rb0 + k);
        g_base[b] = run;
        run += g_cnt[b];
    }
}

// ---------------------------------------------------------------------------
// S3: deposit element indices into their bucket's slot range (order within
// bucket is arbitrary; resolved exactly in S4).
// ---------------------------------------------------------------------------
__global__ void k_fill(const float* __restrict__ scores, int N) {
    int i = blockIdx.x * blockDim.x + threadIdx.x;
    if (i >= N) return;
    unsigned b = __float_as_uint(scores[i]) >> 16;
    int slot = g_base[b] + atomicAdd(&g_fill[b], 1);
    g_members[slot] = i;
}

// ---------------------------------------------------------------------------
// S4: exact stable rank within bucket + scatter into sorted arrays.
// rank = bucketBase + #{ same-bucket j : s_j > s_i || (s_j == s_i && j < i) }
// ---------------------------------------------------------------------------
__global__ void k_place(const float4* __restrict__ boxes,
                        const float* __restrict__ scores, int N) {
    int i = blockIdx.x * blockDim.x + threadIdx.x;
    if (i >= N) return;
    float si = scores[i];
    unsigned b = __float_as_uint(si) >> 16;
    int base = g_base[b];
    int cb   = g_cnt[b];
    int r = base;
    for (int t = 0; t < cb; t++) {
        int j = g_members[base + t];
        if (j == i) continue;
        float sj = scores[j];
        r += (sj > si) || (sj == si && j < i);
    }
    g_sboxes[r]  = boxes[i];
    g_sscores[r] = si;
}

// ---------------------------------------------------------------------------
// K2: pairwise IoU suppression bitmask (upper triangle of 64x64 blocks).
// Column boxes + areas cached in shared. Padding boxes are all-zero ->
// inter=0 -> never suppress.
// ---------------------------------------------------------------------------
__global__ void k_mask(int N, int CB) {
    int cb = blockIdx.x, rb = blockIdx.y;
    if (cb < rb) return;
    __shared__ float4 cbox[64];
    __shared__ float  carea[64];
    int t  = threadIdx.x;
    int cg = cb * 64 + t;
    float4 cv = (cg < N) ? g_sboxes[cg] : make_float4(0.f, 0.f, 0.f, 0.f);
    cbox[t]  = cv;
    carea[t] = (cv.z - cv.x) * (cv.w - cv.y);
    __syncthreads();

    int rg = rb * 64 + t;
    if (rg >= N) return;
    float4 r = g_sboxes[rg];
    float ra = (r.z - r.x) * (r.w - r.y);

    unsigned long long m = 0;
    if (cb > rb) {
        #pragma unroll
        for (int j = 0; j < 64; j++) {
            float4 c = cbox[j];
            float ix1 = fmaxf(r.x, c.x), iy1 = fmaxf(r.y, c.y);
            float ix2 = fminf(r.z, c.z), iy2 = fminf(r.w, c.w);
            float iw = fmaxf(ix2 - ix1, 0.0f), ih = fmaxf(iy2 - iy1, 0.0f);
            float inter = iw * ih;
            float u  = fmaxf(ra + carea[j] - inter, 1e-9f);
            if (inter > 0.5f * u) m |= 1ull << j;
        }
    } else {
        #pragma unroll
        for (int j = 0; j < 64; j++) {
            if (j <= t) continue;  // diagonal: only suppress later boxes
            float4 c = cbox[j];
            float ix1 = fmaxf(r.x, c.x), iy1 = fmaxf(r.y, c.y);
            float ix2 = fminf(r.z, c.z), iy2 = fminf(r.w, c.w);
            float iw = fmaxf(ix2 - ix1, 0.0f), ih = fmaxf(iy2 - iy1, 0.0f);
            float inter = iw * ih;
            float u  = fmaxf(ra + carea[j] - inter, 1e-9f);
            if (inter > 0.5f * u) m |= 1ull << j;
        }
        g_diag[rg] = m;
    }
    g_mask[(size_t)rg * CB + cb] = m;
}

// ---------------------------------------------------------------------------
// K3: serial greedy scan with early termination at MAXP kept.
// ---------------------------------------------------------------------------
__global__ void k_scan(int N, int CB) {
    __shared__ unsigned long long removed[MAXCB];
    __shared__ unsigned long long diagbuf[2][64];
    __shared__ unsigned long long s_keepw;
    __shared__ int s_stop;
    int tid = threadIdx.x;

    for (int w = tid; w < CB; w += blockDim.x) removed[w] = 0ull;
    if (tid < 64) diagbuf[0][tid] = (tid < N) ? g_diag[tid] : 0ull;
    if (tid == 0) s_stop = 0;
    __syncthreads();

    int total = 0;
    int cstop = CB;

    for (int c = 0; c < CB; c++) {
        const unsigned long long* d = diagbuf[c & 1];

        if (tid == 0) {
            unsigned long long rem = removed[c];
            int valid = N - c * 64;
            unsigned long long vmask =
                (valid >= 64) ? ~0ull : ((valid <= 0) ? 0ull : ((1ull << valid) - 1ull));
            unsigned long long pending = ~rem & vmask;
            unsigned long long kp = 0ull;
            while (pending) {
                int i = __ffsll((long long)pending) - 1;
                kp |= 1ull << i;
                pending &= ~d[i];
                pending &= pending - 1ull;
            }
            g_keep[c]   = kp;
            g_prefix[c] = total;
            total += __popcll(kp);
            s_keepw = kp;
            if (total >= MAXP) s_stop = 1;
        }
        __syncthreads();

        if (s_stop) { cstop = c + 1; break; }
        unsigned long long kp = s_keepw;

        int w = c + 1 + tid;
        if (w < CB && kp) {
            const unsigned long long* mp = g_mask + w;
            long long cbase = (long long)c * 64;
            unsigned long long acc = removed[w];
            unsigned long long k = kp;
            while (k) {
                int i0 = __ffsll((long long)k) - 1; k &= k - 1ull;
                int i1 = -1, i2 = -1, i3 = -1;
                if (k) { i1 = __ffsll((long long)k) - 1; k &= k - 1ull; }
                if (k) { i2 = __ffsll((long long)k) - 1; k &= k - 1ull; }
                if (k) { i3 = __ffsll((long long)k) - 1; k &= k - 1ull; }
                unsigned long long a0 = mp[(cbase + i0) * CB];
                unsigned long long a1 = (i1 >= 0) ? mp[(cbase + i1) * CB] : 0ull;
                unsigned long long a2 = (i2 >= 0) ? mp[(cbase + i2) * CB] : 0ull;
                unsigned long long a3 = (i3 >= 0) ? mp[(cbase + i3) * CB] : 0ull;
                acc |= a0 | a1 | a2 | a3;
            }
            removed[w] = acc;
        }

        if (tid >= 192 && c + 1 < CB) {
            int g = (c + 1) * 64 + (tid - 192);
            diagbuf[(c + 1) & 1][tid - 192] = (g < N) ? g_diag[g] : 0ull;
        }
        __syncthreads();
    }

    for (int c2 = cstop + tid; c2 < CB; c2 += blockDim.x) g_keep[c2] = 0ull;
}

// ---------------------------------------------------------------------------
// K4: apply MAX_PROPOSALS cutoff and emit outputs:
//   out[0 : 4N) boxes | out[4N : 5N) scores | out[5N : 6N) keep as 0/1
// ---------------------------------------------------------------------------
__global__ void k_out(float* __restrict__ out, int N) {
    int p = blockIdx.x * blockDim.x + threadIdx.x;
    if (p >= N) return;
    int c = p >> 6, i = p & 63;
    unsigned long long kw = g_keep[c];
    bool kept = (kw >> i) & 1ull;
    int r = g_prefix[c] + __popcll(kw & ((1ull << i) - 1ull));
    bool fin = kept && (r < MAXP);

    float4 b = fin ? g_sboxes[p] : make_float4(0.f, 0.f, 0.f, 0.f);
    ((float4*)out)[p] = b;
    out[4 * N + p] = fin ? g_sscores[p] : 0.0f;
    out[5 * N + p] = fin ? 1.0f : 0.0f;
}

// ---------------------------------------------------------------------------
extern "C" void kernel_launch(void* const* d_in, const int* in_sizes, int n_in,
                              void* d_out, int out_size) {
    const float4* boxes  = (const float4*)d_in[0];
    const float*  scores = (const float*)d_in[1];
    int N  = in_sizes[1];
    int CB = (N + 63) / 64;

    k_clear<<<NBUCK / 256, 256>>>();
    k_hist<<<(N + 255) / 256, 256>>>(scores, N);
    k_scanhist<<<1, 1024>>>();
    k_fill<<<(N + 255) / 256, 256>>>(scores, N);
    k_place<<<(N + 255) / 256, 256>>>(boxes, scores, N);

    dim3 g2(CB, CB);
    k_mask<<<g2, 64>>>(N, CB);

    k_scan<<<1, 256>>>(N, CB);

    k_out<<<(N + 255) / 256, 256>>>((float*)d_out, N);
}

// round 5
// speedup vs baseline: 1.5473x; 1.5473x over previous
#include <cuda_runtime.h>

#define MAXN   10048
#define MAXCB  157
#define MAXP   1000
#define NBUCK  16384

// ---- static device scratch (no allocations allowed) ----
__device__ unsigned long long g_mask[(size_t)MAXN * MAXCB];  // suppression bitmask rows
__device__ unsigned long long g_diag[MAXN];                  // compact diagonal-block masks
__device__ float4             g_sboxes[MAXN];                // boxes in sorted order
__device__ float              g_sscores[MAXN];               // scores in sorted order
__device__ unsigned long long g_keep[MAXCB];                 // keep bits per 64-chunk
__device__ int                g_prefix[MAXCB];               // kept-count prefix per chunk
__device__ int                g_cnt[NBUCK];                  // bucket histogram
__device__ int                g_fill[NBUCK];                 // bucket fill cursors
__device__ int                g_base[NBUCK];                 // bucket base (descending order)
__device__ int                g_members[MAXN];               // indices grouped by bucket

__device__ __forceinline__ unsigned bucket_of(float s) {
    int b = (int)(s * 16384.0f);           // monotone for s >= 0
    b = max(0, min(NBUCK - 1, b));
    return (unsigned)b;
}

// ---------------------------------------------------------------------------
// S0: clear histogram + fill cursors (graph replays reuse static buffers)
// ---------------------------------------------------------------------------
__global__ void k_clear() {
    int i = blockIdx.x * blockDim.x + threadIdx.x;
    if (i < NBUCK) { g_cnt[i] = 0; g_fill[i] = 0; }
}

// ---------------------------------------------------------------------------
// S1: histogram of value buckets
// ---------------------------------------------------------------------------
__global__ void k_hist(const float* __restrict__ scores, int N) {
    int i = blockIdx.x * blockDim.x + threadIdx.x;
    if (i >= N) return;
    atomicAdd(&g_cnt[bucket_of(scores[i])], 1);
}

// ---------------------------------------------------------------------------
// S2: exclusive scan over buckets in DESCENDING bucket order, COALESCED.
// Processes 16 contiguous chunks of 1024 buckets from high to low; within a
// chunk, thread t owns bucket (chunkHigh - t) -> descending rank order, but
// loads/stores hit consecutive addresses (coalesced).
// ---------------------------------------------------------------------------
__global__ void k_scanhist() {
    __shared__ int wsum[32];
    int t = threadIdx.x;
    int lane = t & 31, wid = t >> 5;
    int cbase = 0;  // #elements in all higher chunks (tracked by every thread)

    for (int k = 0; k < NBUCK / 1024; k++) {
        int b = NBUCK - 1 - (k * 1024 + t);   // descending, coalesced
        int v = g_cnt[b];
        // inclusive warp scan in t-order (t=0 = highest bucket first)
        int x = v;
        #pragma unroll
        for (int off = 1; off < 32; off <<= 1) {
            int y = __shfl_up_sync(~0u, x, off);
            if (lane >= off) x += y;
        }
        if (lane == 31) wsum[wid] = x;
        __syncthreads();
        if (wid == 0) {
            int s = wsum[lane];
            #pragma unroll
            for (int off = 1; off < 32; off <<= 1) {
                int y = __shfl_up_sync(~0u, s, off);
                if (lane >= off) s += y;
            }
            wsum[lane] = s;
        }
        __syncthreads();
        int excl = cbase + (x - v) + (wid ? wsum[wid - 1] : 0);
        g_base[b] = excl;
        cbase += wsum[31];      // chunk total (every thread tracks it)
        __syncthreads();        // protect wsum for next iteration
    }
}

// ---------------------------------------------------------------------------
// S3: deposit element indices into their bucket's slot range
// ---------------------------------------------------------------------------
__global__ void k_fill(const float* __restrict__ scores, int N) {
    int i = blockIdx.x * blockDim.x + threadIdx.x;
    if (i >= N) return;
    unsigned b = bucket_of(scores[i]);
    int slot = g_base[b] + atomicAdd(&g_fill[b], 1);
    g_members[slot] = i;
}

// ---------------------------------------------------------------------------
// S4: exact stable rank within bucket + scatter into sorted arrays.
// rank = bucketBase + #{ same-bucket j : s_j > s_i || (s_j == s_i && j < i) }
// ---------------------------------------------------------------------------
__global__ void k_place(const float4* __restrict__ boxes,
                        const float* __restrict__ scores, int N) {
    int i = blockIdx.x * blockDim.x + threadIdx.x;
    if (i >= N) return;
    float si = scores[i];
    unsigned b = bucket_of(si);
    int base = g_base[b];
    int cb   = g_cnt[b];
    int r = base;
    for (int t = 0; t < cb; t++) {
        int j = g_members[base + t];
        if (j == i) continue;
        float sj = scores[j];
        r += (sj > si) || (sj == si && j < i);
    }
    g_sboxes[r]  = boxes[i];
    g_sscores[r] = si;
}

// ---------------------------------------------------------------------------
// K2: pairwise IoU suppression bitmask (upper triangle of 64x64 blocks).
// ---------------------------------------------------------------------------
__global__ void k_mask(int N, int CB) {
    int cb = blockIdx.x, rb = blockIdx.y;
    if (cb < rb) return;
    __shared__ float4 cbox[64];
    __shared__ float  carea[64];
    int t  = threadIdx.x;
    int cg = cb * 64 + t;
    float4 cv = (cg < N) ? g_sboxes[cg] : make_float4(0.f, 0.f, 0.f, 0.f);
    cbox[t]  = cv;
    carea[t] = (cv.z - cv.x) * (cv.w - cv.y);
    __syncthreads();

    int rg = rb * 64 + t;
    if (rg >= N) return;
    float4 r = g_sboxes[rg];
    float ra = (r.z - r.x) * (r.w - r.y);

    unsigned long long m = 0;
    if (cb > rb) {
        #pragma unroll
        for (int j = 0; j < 64; j++) {
            float4 c = cbox[j];
            float ix1 = fmaxf(r.x, c.x), iy1 = fmaxf(r.y, c.y);
            float ix2 = fminf(r.z, c.z), iy2 = fminf(r.w, c.w);
            float iw = fmaxf(ix2 - ix1, 0.0f), ih = fmaxf(iy2 - iy1, 0.0f);
            float inter = iw * ih;
            float u  = fmaxf(ra + carea[j] - inter, 1e-9f);
            if (inter > 0.5f * u) m |= 1ull << j;
        }
    } else {
        #pragma unroll
        for (int j = 0; j < 64; j++) {
            if (j <= t) continue;  // diagonal: only suppress later boxes
            float4 c = cbox[j];
            float ix1 = fmaxf(r.x, c.x), iy1 = fmaxf(r.y, c.y);
            float ix2 = fminf(r.z, c.z), iy2 = fminf(r.w, c.w);
            float iw = fmaxf(ix2 - ix1, 0.0f), ih = fmaxf(iy2 - iy1, 0.0f);
            float inter = iw * ih;
            float u  = fmaxf(ra + carea[j] - inter, 1e-9f);
            if (inter > 0.5f * u) m |= 1ull << j;
        }
        g_diag[rg] = m;
    }
    g_mask[(size_t)rg * CB + cb] = m;
}

// ---------------------------------------------------------------------------
// K3: pipelined greedy scan with early termination.
// Each iteration c: all threads gather suppression for word w=c+1+tid from
// chunk c's kept boxes; thread 0 continues straight into phase A for chunk
// c+1 using its freshly-gathered word. klist/kp/diag double-buffered.
// ---------------------------------------------------------------------------
__global__ void k_scan(int N, int CB) {
    __shared__ unsigned long long removed[MAXCB];
    __shared__ unsigned long long diagbuf[2][64];
    __shared__ int klist[2][64];
    __shared__ int s_nk[2];
    __shared__ unsigned long long s_kp[2];
    __shared__ int s_stop;
    __shared__ int s_cstop;
    int tid = threadIdx.x;

    for (int w = tid; w < CB; w += blockDim.x) removed[w] = 0ull;
    if (tid < 64) {
        diagbuf[0][tid] = (tid < N) ? g_diag[tid] : 0ull;
        int g1 = 64 + tid;
        diagbuf[1][tid] = (CB > 1 && g1 < N) ? g_diag[g1] : 0ull;
    }
    if (tid == 0) { s_stop = 0; s_cstop = CB; }
    __syncthreads();

    int total = 0;  // thread 0 only

    // phase A for chunk 0
    if (tid == 0) {
        const unsigned long long* d = diagbuf[0];
        int valid = min(N, 64);
        unsigned long long vmask = (valid >= 64) ? ~0ull : ((1ull << valid) - 1ull);
        unsigned long long pending = vmask;
        unsigned long long kp = 0ull;
        int n = 0;
        while (pending) {
            int i = __ffsll((long long)pending) - 1;
            kp |= 1ull << i;
            klist[0][n++] = i;
            pending &= ~d[i];
            pending &= pending - 1ull;
        }
        g_keep[0] = kp; g_prefix[0] = 0;
        total = __popcll(kp);
        s_kp[0] = kp; s_nk[0] = n;
        if (total >= MAXP) { s_stop = 1; s_cstop = 1; }
    }
    __syncthreads();

    for (int c = 0; c + 1 < CB; c++) {
        if (s_stop) break;
        int pb = c & 1;
        int nk = s_nk[pb];
        const int* kl = klist[pb];
        int w = c + 1 + tid;

        unsigned long long acc = 0ull;
        if (w < CB) {
            acc = removed[w];
            const unsigned long long* mp = g_mask + w;
            size_t cb64 = (size_t)c * 64;
            int t = 0;
            while (t < nk) {
                unsigned long long a = 0ull;
                #pragma unroll
                for (int u = 0; u < 16; u++) {
                    if (t + u < nk) a |= mp[(cb64 + kl[t + u]) * CB];
                }
                acc |= a;
                t += 16;
            }
        }

        if (tid == 0) {
            // phase A for chunk c+1, rem = freshly gathered acc
            int cc = c + 1;
            const unsigned long long* d = diagbuf[cc & 1];
            int valid = N - cc * 64;
            unsigned long long vmask =
                (valid >= 64) ? ~0ull : ((valid <= 0) ? 0ull : ((1ull << valid) - 1ull));
            unsigned long long pending = ~acc & vmask;
            unsigned long long kp = 0ull;
            int n = 0;
            while (pending) {
                int i = __ffsll((long long)pending) - 1;
                kp |= 1ull << i;
                klist[cc & 1][n++] = i;
                pending &= ~d[i];
                pending &= pending - 1ull;
            }
            g_keep[cc] = kp; g_prefix[cc] = total;
            total += __popcll(kp);
            s_kp[cc & 1] = kp; s_nk[cc & 1] = n;
            if (total >= MAXP) { s_stop = 1; s_cstop = cc + 1; }
        } else if (w < CB) {
            removed[w] = acc;
        }

        // prefetch diag masks for chunk c+2 (tid>=192 never gathers: w>=193>CB)
        if (tid >= 192 && c + 2 < CB) {
            int g = (c + 2) * 64 + (tid - 192);
            diagbuf[(c + 2) & 1][tid - 192] = (g < N) ? g_diag[g] : 0ull;
        }
        __syncthreads();
    }

    int cstop = s_cstop;
    for (int c2 = cstop + tid; c2 < CB; c2 += blockDim.x) g_keep[c2] = 0ull;
}

// ---------------------------------------------------------------------------
// K4: apply MAX_PROPOSALS cutoff and emit outputs:
//   out[0 : 4N) boxes | out[4N : 5N) scores | out[5N : 6N) keep as 0/1
// ---------------------------------------------------------------------------
__global__ void k_out(float* __restrict__ out, int N) {
    int p = blockIdx.x * blockDim.x + threadIdx.x;
    if (p >= N) return;
    int c = p >> 6, i = p & 63;
    unsigned long long kw = g_keep[c];
    bool kept = (kw >> i) & 1ull;
    int r = g_prefix[c] + __popcll(kw & ((1ull << i) - 1ull));
    bool fin = kept && (r < MAXP);

    float4 b = fin ? g_sboxes[p] : make_float4(0.f, 0.f, 0.f, 0.f);
    ((float4*)out)[p] = b;
    out[4 * N + p] = fin ? g_sscores[p] : 0.0f;
    out[5 * N + p] = fin ? 1.0f : 0.0f;
}

// ---------------------------------------------------------------------------
extern "C" void kernel_launch(void* const* d_in, const int* in_sizes, int n_in,
                              void* d_out, int out_size) {
    const float4* boxes  = (const float4*)d_in[0];
    const float*  scores = (const float*)d_in[1];
    int N  = in_sizes[1];
    int CB = (N + 63) / 64;

    k_clear<<<NBUCK / 256, 256>>>();
    k_hist<<<(N + 255) / 256, 256>>>(scores, N);
    k_scanhist<<<1, 1024>>>();
    k_fill<<<(N + 255) / 256, 256>>>(scores, N);
    k_place<<<(N + 255) / 256, 256>>>(boxes, scores, N);

    dim3 g2(CB, CB);
    k_mask<<<g2, 64>>>(N, CB);

    k_scan<<<1, 256>>>(N, CB);

    k_out<<<(N + 255) / 256, 256>>>((float*)d_out, N);
}